// round 7
// baseline (speedup 1.0000x reference)
#include <cuda_runtime.h>
#include <cstdint>

typedef unsigned long long u64;
typedef unsigned int u32;

// ===================== f32x2 helpers =====================
__device__ __forceinline__ u64 fma2(u64 a, u64 b, u64 c) {
    u64 d; asm("fma.rn.f32x2 %0, %1, %2, %3;" : "=l"(d) : "l"(a), "l"(b), "l"(c)); return d;
}
__device__ __forceinline__ u64 pack2(float lo, float hi) {
    u64 d; asm("mov.b64 %0, {%1, %2};" : "=l"(d) : "f"(lo), "f"(hi)); return d;
}
__device__ __forceinline__ float2 unpack2(u64 v) {
    float2 r; asm("mov.b64 {%0, %1}, %2;" : "=f"(r.x), "=f"(r.y) : "l"(v)); return r;
}

// Scratch hidden state h [8192 x 1024]
__device__ float g_h[8192 * 1024];

// ===================== mma.sync helpers =====================
__device__ __forceinline__ u32 smem_u32(const void* p) {
    u32 a;
    asm("{ .reg .u64 t; cvta.to.shared.u64 t, %1; cvt.u32.u64 %0, t; }" : "=r"(a) : "l"(p));
    return a;
}

#define LDSM4(r, addr) \
    asm volatile("ldmatrix.sync.aligned.m8n8.x4.shared.b16 {%0,%1,%2,%3}, [%4];" \
        : "=r"((r)[0]), "=r"((r)[1]), "=r"((r)[2]), "=r"((r)[3]) : "r"(addr))

#define MMA_BF16(c, a, b) \
    asm volatile("mma.sync.aligned.m16n8k16.row.col.f32.bf16.bf16.f32 " \
        "{%0,%1,%2,%3}, {%4,%5,%6,%7}, {%8,%9}, {%0,%1,%2,%3};" \
        : "+f"((c)[0]), "+f"((c)[1]), "+f"((c)[2]), "+f"((c)[3]) \
        : "r"((a)[0]), "r"((a)[1]), "r"((a)[2]), "r"((a)[3]), \
          "r"((b)[0]), "r"((b)[1]))

// split float pair -> bf16 hi-plane word + lo-plane word (lo16 = first elem)
__device__ __forceinline__ void split2(float x, float y, u32& hi, u32& lo) {
    u32 h;
    asm("cvt.rn.bf16x2.f32 %0, %1, %2;" : "=r"(h) : "f"(y), "f"(x));
    float hx = __uint_as_float(h << 16);
    float hy = __uint_as_float(h & 0xFFFF0000u);
    float lx = x - hx;
    float ly = y - hy;
    u32 l;
    asm("cvt.rn.bf16x2.f32 %0, %1, %2;" : "=r"(l) : "f"(ly), "f"(lx));
    hi = h; lo = l;
}

// smem geometry: BK=16 -> rows of 16 bf16 data in 24-ushort (48B) stride.
// 48B stride is 16B-aligned and ldmatrix conflict-free.
static constexpr int ROW_US  = 24;                  // ushorts per row
static constexpr int PLANE_B = 128 * ROW_US * 2;    // 6144 bytes per plane
static constexpr int STAGE_B = 4 * PLANE_B;         // Ah, Al, Bh, Bl = 24576
static constexpr int GEMM_SMEM = 2 * STAGE_B;       // 49152 dynamic

// ---------------------------------------------------------------------------
// Kernel 1: h = x @ W1^T + b1, bf16-split (3 products) mma.sync.
// CTA 128x128, BK=16 (784 = 49*16, no bounds checks), 4 warps (2x2),
// warp tile 64x64, smem double-buffered, 2 CTAs/SM.
// ---------------------------------------------------------------------------
__global__ void __launch_bounds__(128, 2) gemm1_mma(
    const float* __restrict__ A, const float* __restrict__ W,
    const float* __restrict__ bias)
{
    extern __shared__ __align__(16) char dsm[];
    const u32 sb = smem_u32(dsm);

    const int tid = threadIdx.x;
    const int wid = tid >> 5, lane = tid & 31;
    const int wm = wid >> 1;       // 0..1  (64-row band)
    const int wn = wid & 1;        // 0..1  (64-col band)
    const int bm = blockIdx.y * 128, bn = blockIdx.x * 128;

    // loaders: thread t -> row t (A and B), 16 fp32 columns = 4 float4
    const float* Ap = A + (size_t)(bm + tid) * 784;
    const float* Wp = W + (size_t)(bn + tid) * 784;

    float4 av[4], bv[4];
    auto LOAD = [&](int kt) {
        const int k0 = kt * 16;
#pragma unroll
        for (int j = 0; j < 4; j++) {
            av[j] = *(const float4*)(Ap + k0 + 4 * j);
            bv[j] = *(const float4*)(Wp + k0 + 4 * j);
        }
    };
    auto STORE = [&](int s) {
        char* base = dsm + s * STAGE_B;
        unsigned short* pAh = (unsigned short*)(base);
        unsigned short* pAl = (unsigned short*)(base + PLANE_B);
        unsigned short* pBh = (unsigned short*)(base + 2 * PLANE_B);
        unsigned short* pBl = (unsigned short*)(base + 3 * PLANE_B);
        const int off = tid * ROW_US;
#pragma unroll
        for (int j = 0; j < 4; j++) {
            u32 h01, l01, h23, l23;
            split2(av[j].x, av[j].y, h01, l01);
            split2(av[j].z, av[j].w, h23, l23);
            *(uint2*)&pAh[off + 4 * j] = make_uint2(h01, h23);
            *(uint2*)&pAl[off + 4 * j] = make_uint2(l01, l23);
            split2(bv[j].x, bv[j].y, h01, l01);
            split2(bv[j].z, bv[j].w, h23, l23);
            *(uint2*)&pBh[off + 4 * j] = make_uint2(h01, h23);
            *(uint2*)&pBl[off + 4 * j] = make_uint2(l01, l23);
        }
    };

    float c[4][8][4];
#pragma unroll
    for (int mf = 0; mf < 4; mf++)
#pragma unroll
        for (int nf = 0; nf < 8; nf++)
#pragma unroll
            for (int r = 0; r < 4; r++) c[mf][nf][r] = 0.0f;

    // ldmatrix per-lane byte offsets within a plane (48B row stride)
    const u32 a_lm = (u32)((wm * 64 + (lane & 15)) * 48 + (lane >> 4) * 16);
    const u32 b_lm = (u32)((wn * 64 + ((lane & 16) >> 1) + (lane & 7)) * 48 + ((lane >> 3) & 1) * 16);

    auto COMPUTE = [&](int s) {
        const u32 bufb = sb + s * STAGE_B;
        u32 ah[4][4], al[4][4];
        const u32 aoff = bufb + a_lm;
#pragma unroll
        for (int mf = 0; mf < 4; mf++) {
            LDSM4(ah[mf], aoff + mf * 768);
            LDSM4(al[mf], aoff + PLANE_B + mf * 768);
        }
        const u32 boff = bufb + 2 * PLANE_B + b_lm;
#pragma unroll
        for (int g = 0; g < 4; g++) {
            u32 th[4], tl[4];
            LDSM4(th, boff + g * 768);
            LDSM4(tl, boff + PLANE_B + g * 768);
            u32 bh0[2] = { th[0], th[1] }, bh1[2] = { th[2], th[3] };
            u32 bl0[2] = { tl[0], tl[1] }, bl1[2] = { tl[2], tl[3] };
#pragma unroll
            for (int mf = 0; mf < 4; mf++) {
                MMA_BF16(c[mf][2 * g],     ah[mf], bh0);
                MMA_BF16(c[mf][2 * g],     ah[mf], bl0);
                MMA_BF16(c[mf][2 * g],     al[mf], bh0);
                MMA_BF16(c[mf][2 * g + 1], ah[mf], bh1);
                MMA_BF16(c[mf][2 * g + 1], ah[mf], bl1);
                MMA_BF16(c[mf][2 * g + 1], al[mf], bh1);
            }
        }
    };

    // prologue: tile0 stored, tile1 staged in regs
    LOAD(0);
    STORE(0);
    LOAD(1);
    __syncthreads();

#pragma unroll 1
    for (int kt = 0; kt < 49; kt++) {
        const int s = kt & 1;
        if (kt < 48) {
            STORE(s ^ 1);            // tile kt+1 (in regs) -> other buffer
            if (kt < 47) LOAD(kt + 2);
        }
        COMPUTE(s);
        __syncthreads();
    }

    // epilogue: C + bias -> g_h
#pragma unroll
    for (int mf = 0; mf < 4; mf++) {
#pragma unroll
        for (int nf = 0; nf < 8; nf++) {
            const int row = bm + wm * 64 + mf * 16 + (lane >> 2);
            const int col = bn + wn * 64 + nf * 8 + (lane & 3) * 2;
            const float b0 = bias[col], b1 = bias[col + 1];
            float2 v0 = make_float2(c[mf][nf][0] + b0, c[mf][nf][1] + b1);
            float2 v1 = make_float2(c[mf][nf][2] + b0, c[mf][nf][3] + b1);
            *(float2*)(g_h + (size_t)row * 1024 + col) = v0;
            *(float2*)(g_h + (size_t)(row + 8) * 1024 + col) = v1;
        }
    }
}

// ---------------------------------------------------------------------------
// Kernel 2 (fused, warp-private): RK4 Lorenz96 over [0,1], h=1/20 (20 steps),
// then logits + log_softmax. One WARP owns one pair of batch rows packed in
// f32x2; each lane owns 32 features (32 lanes x 32 = 1024, wraps in-warp).
// Halo exchange via __shfl_sync only — no smem, no barriers.
// ---------------------------------------------------------------------------
__global__ void __launch_bounds__(128) rk4_head_kernel(
    const float* __restrict__ W2, const float* __restrict__ b2,
    float* __restrict__ out)
{
    const int lane = threadIdx.x & 31;
    const int w = threadIdx.x >> 5;
    const size_t rp = (size_t)blockIdx.x * 4 + w;        // row pair 0..4095
    const float* p0 = g_h + rp * 2048 + lane * 32;
    const float* p1 = p0 + 1024;

    const float hf = 1.0f / 20.0f;
    const u64 NEG1 = pack2(-1.0f, -1.0f);
    const u64 F2   = pack2(8.0f, 8.0f);
    const u64 H05  = pack2(hf * 0.5f, hf * 0.5f);
    const u64 H1   = pack2(hf, hf);
    const u64 H6   = pack2(hf / 6.0f, hf / 6.0f);
    const u64 H3   = pack2(hf / 3.0f, hf / 3.0f);

    const int lp = (lane + 31) & 31;
    const int ln = (lane + 1) & 31;

    u64 x[32], y[32], xa[32];
#pragma unroll
    for (int j = 0; j < 8; j++) {
        float4 a = ((const float4*)p0)[j];
        float4 b = ((const float4*)p1)[j];
        x[4 * j + 0] = pack2(a.x, b.x);
        x[4 * j + 1] = pack2(a.y, b.y);
        x[4 * j + 2] = pack2(a.z, b.z);
        x[4 * j + 3] = pack2(a.w, b.w);
    }

#pragma unroll 1
    for (int s = 0; s < 20; s++) {
        {   // stage 1: k1 from x
            u64 ym2 = __shfl_sync(0xFFFFFFFFu, x[30], lp);
            u64 ym1 = __shfl_sync(0xFFFFFFFFu, x[31], lp);
            u64 hp1 = __shfl_sync(0xFFFFFFFFu, x[0],  ln);
#pragma unroll
            for (int i = 0; i < 32; i++) {
                u64 vc = x[i];
                u64 vp = (i < 31) ? x[i + 1] : hp1;
                u64 k  = fma2(fma2(ym2, NEG1, vp), ym1, fma2(vc, NEG1, F2));
                xa[i]  = fma2(k, H6, x[i]);
                y[i]   = fma2(k, H05, x[i]);
                ym2 = ym1; ym1 = vc;
            }
        }
        {   // stage 2: k2 from y
            u64 ym2 = __shfl_sync(0xFFFFFFFFu, y[30], lp);
            u64 ym1 = __shfl_sync(0xFFFFFFFFu, y[31], lp);
            u64 hp1 = __shfl_sync(0xFFFFFFFFu, y[0],  ln);
#pragma unroll
            for (int i = 0; i < 32; i++) {
                u64 vc = y[i];
                u64 vp = (i < 31) ? y[i + 1] : hp1;
                u64 k  = fma2(fma2(ym2, NEG1, vp), ym1, fma2(vc, NEG1, F2));
                xa[i]  = fma2(k, H3, xa[i]);
                y[i]   = fma2(k, H05, x[i]);
                ym2 = ym1; ym1 = vc;
            }
        }
        {   // stage 3: k3 from y
            u64 ym2 = __shfl_sync(0xFFFFFFFFu, y[30], lp);
            u64 ym1 = __shfl_sync(0xFFFFFFFFu, y[31], lp);
            u64 hp1 = __shfl_sync(0xFFFFFFFFu, y[0],  ln);
#pragma unroll
            for (int i = 0; i < 32; i++) {
                u64 vc = y[i];
                u64 vp = (i < 31) ? y[i + 1] : hp1;
                u64 k  = fma2(fma2(ym2, NEG1, vp), ym1, fma2(vc, NEG1, F2));
                xa[i]  = fma2(k, H3, xa[i]);
                y[i]   = fma2(k, H1, x[i]);
                ym2 = ym1; ym1 = vc;
            }
        }
        {   // stage 4: k4 from y; x = xa + h/6 k4
            u64 ym2 = __shfl_sync(0xFFFFFFFFu, y[30], lp);
            u64 ym1 = __shfl_sync(0xFFFFFFFFu, y[31], lp);
            u64 hp1 = __shfl_sync(0xFFFFFFFFu, y[0],  ln);
#pragma unroll
            for (int i = 0; i < 32; i++) {
                u64 vc = y[i];
                u64 vp = (i < 31) ? y[i + 1] : hp1;
                u64 k  = fma2(fma2(ym2, NEG1, vp), ym1, fma2(vc, NEG1, F2));
                x[i]   = fma2(k, H6, xa[i]);
                ym2 = ym1; ym1 = vc;
            }
        }
    }

    // ---- fused head: logits + log_softmax, all within the warp ----
    float lx[10], ly[10];
#pragma unroll
    for (int o = 0; o < 10; o++) {
        const float4* w4 = (const float4*)(W2 + (size_t)o * 1024 + lane * 32);
        u64 a = 0ull;
#pragma unroll
        for (int j = 0; j < 8; j++) {
            float4 wv = w4[j];
            a = fma2(x[4 * j + 0], pack2(wv.x, wv.x), a);
            a = fma2(x[4 * j + 1], pack2(wv.y, wv.y), a);
            a = fma2(x[4 * j + 2], pack2(wv.z, wv.z), a);
            a = fma2(x[4 * j + 3], pack2(wv.w, wv.w), a);
        }
        float2 v = unpack2(a);
#pragma unroll
        for (int off = 16; off > 0; off >>= 1) {
            v.x += __shfl_xor_sync(0xFFFFFFFFu, v.x, off);
            v.y += __shfl_xor_sync(0xFFFFFFFFu, v.y, off);
        }
        lx[o] = v.x + b2[o];
        ly[o] = v.y + b2[o];
    }

    float mx = -1e30f, my = -1e30f;
#pragma unroll
    for (int o = 0; o < 10; o++) { mx = fmaxf(mx, lx[o]); my = fmaxf(my, ly[o]); }
    float sx = 0.0f, sy = 0.0f;
#pragma unroll
    for (int o = 0; o < 10; o++) { sx += expf(lx[o] - mx); sy += expf(ly[o] - my); }
    const float lsex = logf(sx) + mx;
    const float lsey = logf(sy) + my;

    float ox = 0.0f, oy = 0.0f;
#pragma unroll
    for (int o = 0; o < 10; o++) {
        if (lane == o) { ox = lx[o] - lsex; oy = ly[o] - lsey; }
    }
    if (lane < 10) {
        out[rp * 20 + lane]      = ox;
        out[rp * 20 + 10 + lane] = oy;
    }
}

// ---------------------------------------------------------------------------
extern "C" void kernel_launch(void* const* d_in, const int* in_sizes, int n_in,
                              void* d_out, int out_size)
{
    const float* x  = (const float*)d_in[0];  // [8192, 784]
    const float* W1 = (const float*)d_in[1];  // [1024, 784]
    const float* b1 = (const float*)d_in[2];  // [1024]
    const float* W2 = (const float*)d_in[3];  // [10, 1024]
    const float* b2 = (const float*)d_in[4];  // [10]
    float* out = (float*)d_out;               // [8192, 10]

    cudaFuncSetAttribute(gemm1_mma, cudaFuncAttributeMaxDynamicSharedMemorySize, GEMM_SMEM);

    dim3 g1(1024 / 128, 8192 / 128);          // (8, 64)
    gemm1_mma<<<g1, 128, GEMM_SMEM>>>(x, W1, b1);
    rk4_head_kernel<<<8192 / 8, 128>>>(W2, b2, out);
}

// round 8
// speedup vs baseline: 1.1536x; 1.1536x over previous
#include <cuda_runtime.h>
#include <cstdint>

typedef unsigned long long u64;
typedef unsigned int u32;

// ===================== f32x2 helpers =====================
__device__ __forceinline__ u64 fma2(u64 a, u64 b, u64 c) {
    u64 d; asm("fma.rn.f32x2 %0, %1, %2, %3;" : "=l"(d) : "l"(a), "l"(b), "l"(c)); return d;
}
__device__ __forceinline__ u64 pack2(float lo, float hi) {
    u64 d; asm("mov.b64 %0, {%1, %2};" : "=l"(d) : "f"(lo), "f"(hi)); return d;
}
__device__ __forceinline__ float2 unpack2(u64 v) {
    float2 r; asm("mov.b64 {%0, %1}, %2;" : "=f"(r.x), "=f"(r.y) : "l"(v)); return r;
}

// Scratch hidden state h [8192 x 1024]
__device__ float g_h[8192 * 1024];

// ===================== mma.sync helpers =====================
__device__ __forceinline__ u32 smem_u32(const void* p) {
    u32 a;
    asm("{ .reg .u64 t; cvta.to.shared.u64 t, %1; cvt.u32.u64 %0, t; }" : "=r"(a) : "l"(p));
    return a;
}

#define LDSM4(r, addr) \
    asm volatile("ldmatrix.sync.aligned.m8n8.x4.shared.b16 {%0,%1,%2,%3}, [%4];" \
        : "=r"((r)[0]), "=r"((r)[1]), "=r"((r)[2]), "=r"((r)[3]) : "r"(addr))

#define MMA_BF16(c, a, b) \
    asm volatile("mma.sync.aligned.m16n8k16.row.col.f32.bf16.bf16.f32 " \
        "{%0,%1,%2,%3}, {%4,%5,%6,%7}, {%8,%9}, {%0,%1,%2,%3};" \
        : "+f"((c)[0]), "+f"((c)[1]), "+f"((c)[2]), "+f"((c)[3]) \
        : "r"((a)[0]), "r"((a)[1]), "r"((a)[2]), "r"((a)[3]), \
          "r"((b)[0]), "r"((b)[1]))

// split float pair -> bf16 hi-plane word + lo-plane word (lo16 = first elem)
__device__ __forceinline__ void split2(float x, float y, u32& hi, u32& lo) {
    u32 h;
    asm("cvt.rn.bf16x2.f32 %0, %1, %2;" : "=r"(h) : "f"(y), "f"(x));
    float hx = __uint_as_float(h << 16);
    float hy = __uint_as_float(h & 0xFFFF0000u);
    float lx = x - hx;
    float ly = y - hy;
    u32 l;
    asm("cvt.rn.bf16x2.f32 %0, %1, %2;" : "=r"(l) : "f"(ly), "f"(lx));
    hi = h; lo = l;
}

// smem geometry: BK=16 -> rows of 16 bf16 in 24-ushort (48B) stride.
static constexpr int ROW_US  = 24;
static constexpr int PLANE_B = 128 * ROW_US * 2;    // 6144 B per plane
static constexpr int STAGE_B = 4 * PLANE_B;         // Ah, Al, Bh, Bl = 24576
static constexpr int GEMM_SMEM = 2 * STAGE_B;       // 49152 dynamic

// ---------------------------------------------------------------------------
// Kernel 1: h = x @ W1^T + b1, bf16-split (3 products) mma.sync.
// CTA 128x128, BK=16 (784 = 49*16), 4 warps (2x2), warp tile 64x64,
// double-buffered, 2 CTAs/SM, A-frag LDSM hoisted across the barrier.
// ---------------------------------------------------------------------------
__global__ void __launch_bounds__(128, 2) gemm1_mma(
    const float* __restrict__ A, const float* __restrict__ W,
    const float* __restrict__ bias)
{
    extern __shared__ __align__(16) char dsm[];
    const u32 sb = smem_u32(dsm);

    const int tid = threadIdx.x;
    const int wid = tid >> 5, lane = tid & 31;
    const int wm = wid >> 1;       // 0..1  (64-row band)
    const int wn = wid & 1;        // 0..1  (64-col band)
    const int bm = blockIdx.y * 128, bn = blockIdx.x * 128;

    // loaders: thread t -> row t (A and B), 16 fp32 columns = 4 float4
    const float* Ap = A + (size_t)(bm + tid) * 784;
    const float* Wp = W + (size_t)(bn + tid) * 784;

    float4 av[4], bv[4];
    auto LOAD = [&](int kt) {
        const int k0 = kt * 16;
#pragma unroll
        for (int j = 0; j < 4; j++) {
            av[j] = *(const float4*)(Ap + k0 + 4 * j);
            bv[j] = *(const float4*)(Wp + k0 + 4 * j);
        }
    };
    auto STORE = [&](int s) {
        char* base = dsm + s * STAGE_B;
        unsigned short* pAh = (unsigned short*)(base);
        unsigned short* pAl = (unsigned short*)(base + PLANE_B);
        unsigned short* pBh = (unsigned short*)(base + 2 * PLANE_B);
        unsigned short* pBl = (unsigned short*)(base + 3 * PLANE_B);
        const int off = tid * ROW_US;
#pragma unroll
        for (int j = 0; j < 4; j++) {
            u32 h01, l01, h23, l23;
            split2(av[j].x, av[j].y, h01, l01);
            split2(av[j].z, av[j].w, h23, l23);
            *(uint2*)&pAh[off + 4 * j] = make_uint2(h01, h23);
            *(uint2*)&pAl[off + 4 * j] = make_uint2(l01, l23);
            split2(bv[j].x, bv[j].y, h01, l01);
            split2(bv[j].z, bv[j].w, h23, l23);
            *(uint2*)&pBh[off + 4 * j] = make_uint2(h01, h23);
            *(uint2*)&pBl[off + 4 * j] = make_uint2(l01, l23);
        }
    };

    float c[4][8][4];
#pragma unroll
    for (int mf = 0; mf < 4; mf++)
#pragma unroll
        for (int nf = 0; nf < 8; nf++)
#pragma unroll
            for (int r = 0; r < 4; r++) c[mf][nf][r] = 0.0f;

    // ldmatrix per-lane byte offsets within a plane (48B row stride)
    const u32 a_lm = (u32)((wm * 64 + (lane & 15)) * 48 + (lane >> 4) * 16);
    const u32 b_lm = (u32)((wn * 64 + ((lane & 16) >> 1) + (lane & 7)) * 48 + ((lane >> 3) & 1) * 16);

    u32 ah[4][4], al[4][4];          // A-frags, live across the barrier
    auto LDA = [&](int s) {
        const u32 aoff = sb + s * STAGE_B + a_lm;
#pragma unroll
        for (int mf = 0; mf < 4; mf++) {
            LDSM4(ah[mf], aoff + mf * 768);
            LDSM4(al[mf], aoff + PLANE_B + mf * 768);
        }
    };
    auto COMPB = [&](int s) {
        const u32 boff = sb + s * STAGE_B + 2 * PLANE_B + b_lm;
#pragma unroll
        for (int g = 0; g < 4; g++) {
            u32 th[4], tl[4];
            LDSM4(th, boff + g * 768);
            LDSM4(tl, boff + PLANE_B + g * 768);
            u32 bh0[2] = { th[0], th[1] }, bh1[2] = { th[2], th[3] };
            u32 bl0[2] = { tl[0], tl[1] }, bl1[2] = { tl[2], tl[3] };
#pragma unroll
            for (int mf = 0; mf < 4; mf++) {
                MMA_BF16(c[mf][2 * g],     ah[mf], bh0);
                MMA_BF16(c[mf][2 * g],     ah[mf], bl0);
                MMA_BF16(c[mf][2 * g],     al[mf], bh0);
                MMA_BF16(c[mf][2 * g + 1], ah[mf], bh1);
                MMA_BF16(c[mf][2 * g + 1], ah[mf], bl1);
                MMA_BF16(c[mf][2 * g + 1], al[mf], bh1);
            }
        }
    };

    // prologue: tile0 stored, tile1 staged in regs, A-frags(buf0) loaded
    LOAD(0);
    STORE(0);
    LOAD(1);
    __syncthreads();
    LDA(0);

#pragma unroll 1
    for (int kt = 0; kt < 49; kt++) {
        const int s = kt & 1;
        if (kt < 48) {
            STORE(s ^ 1);            // tile kt+1 (in regs) -> other buffer
            if (kt < 47) LOAD(kt + 2);
        }
        COMPB(s);                    // uses A-frags preloaded for buffer s
        __syncthreads();
        if (kt < 48) LDA(s ^ 1);     // hoist next tile's A LDSMs across barrier
    }

    // epilogue: C + bias -> g_h
#pragma unroll
    for (int mf = 0; mf < 4; mf++) {
#pragma unroll
        for (int nf = 0; nf < 8; nf++) {
            const int row = bm + wm * 64 + mf * 16 + (lane >> 2);
            const int col = bn + wn * 64 + nf * 8 + (lane & 3) * 2;
            const float b0 = bias[col], b1 = bias[col + 1];
            float2 v0 = make_float2(c[mf][nf][0] + b0, c[mf][nf][1] + b1);
            float2 v1 = make_float2(c[mf][nf][2] + b0, c[mf][nf][3] + b1);
            *(float2*)(g_h + (size_t)row * 1024 + col) = v0;
            *(float2*)(g_h + (size_t)(row + 8) * 1024 + col) = v1;
        }
    }
}

// ---------------------------------------------------------------------------
// Kernel 2 (fused): RK4 Lorenz96 over [0,1] with h=1/16 (16 steps), then
// logits = h @ W2^T + b2 and log_softmax, without writing h back.
// Block = 64 threads = one pair of batch rows packed into f32x2 lanes.
// ---------------------------------------------------------------------------
__global__ void __launch_bounds__(64) rk4_head_kernel(
    const float* __restrict__ W2, const float* __restrict__ b2,
    float* __restrict__ out)
{
    const int t = threadIdx.x;
    const int warp = t >> 5;
    const float* p0 = g_h + (size_t)(2 * blockIdx.x) * 1024 + t * 16;
    const float* p1 = p0 + 1024;

    const float hf = 1.0f / 16.0f;
    const u64 NEG1 = pack2(-1.0f, -1.0f);
    const u64 F2   = pack2(8.0f, 8.0f);
    const u64 H05  = pack2(hf * 0.5f, hf * 0.5f);
    const u64 H1   = pack2(hf, hf);
    const u64 H6   = pack2(hf / 6.0f, hf / 6.0f);
    const u64 H3   = pack2(hf / 3.0f, hf / 3.0f);

    u64 x[16], y[16], xa[16];
#pragma unroll
    for (int i = 0; i < 16; i++) x[i] = pack2(p0[i], p1[i]);

    __shared__ u64 sA[2][64], sB[2][64], sC[2][64];
    __shared__ float2 red[2][10];
    __shared__ float2 lg[10];
    __shared__ float lse2[2];

    const int tl = (t + 63) & 63;
    const int tr = (t + 1) & 63;

    sA[0][t] = x[14]; sB[0][t] = x[15]; sC[0][t] = x[0];
    __syncthreads();
    int pb = 0;

#pragma unroll 1
    for (int s = 0; s < 16; s++) {
        {   // stage 1: k1 from x
            u64 ym2 = sA[pb][tl], ym1 = sB[pb][tl], hp1 = sC[pb][tr];
#pragma unroll
            for (int i = 0; i < 16; i++) {
                u64 vc = x[i];
                u64 vp = (i < 15) ? x[i + 1] : hp1;
                u64 k  = fma2(fma2(ym2, NEG1, vp), ym1, fma2(vc, NEG1, F2));
                xa[i]  = fma2(k, H6, x[i]);
                y[i]   = fma2(k, H05, x[i]);
                ym2 = ym1; ym1 = vc;
            }
            pb ^= 1;
            sA[pb][t] = y[14]; sB[pb][t] = y[15]; sC[pb][t] = y[0];
            __syncthreads();
        }
        {   // stage 2: k2 from y
            u64 ym2 = sA[pb][tl], ym1 = sB[pb][tl], hp1 = sC[pb][tr];
#pragma unroll
            for (int i = 0; i < 16; i++) {
                u64 vc = y[i];
                u64 vp = (i < 15) ? y[i + 1] : hp1;
                u64 k  = fma2(fma2(ym2, NEG1, vp), ym1, fma2(vc, NEG1, F2));
                xa[i]  = fma2(k, H3, xa[i]);
                y[i]   = fma2(k, H05, x[i]);
                ym2 = ym1; ym1 = vc;
            }
            pb ^= 1;
            sA[pb][t] = y[14]; sB[pb][t] = y[15]; sC[pb][t] = y[0];
            __syncthreads();
        }
        {   // stage 3: k3 from y
            u64 ym2 = sA[pb][tl], ym1 = sB[pb][tl], hp1 = sC[pb][tr];
#pragma unroll
            for (int i = 0; i < 16; i++) {
                u64 vc = y[i];
                u64 vp = (i < 15) ? y[i + 1] : hp1;
                u64 k  = fma2(fma2(ym2, NEG1, vp), ym1, fma2(vc, NEG1, F2));
                xa[i]  = fma2(k, H3, xa[i]);
                y[i]   = fma2(k, H1, x[i]);
                ym2 = ym1; ym1 = vc;
            }
            pb ^= 1;
            sA[pb][t] = y[14]; sB[pb][t] = y[15]; sC[pb][t] = y[0];
            __syncthreads();
        }
        {   // stage 4: k4 from y; x = xa + h/6 k4
            u64 ym2 = sA[pb][tl], ym1 = sB[pb][tl], hp1 = sC[pb][tr];
#pragma unroll
            for (int i = 0; i < 16; i++) {
                u64 vc = y[i];
                u64 vp = (i < 15) ? y[i + 1] : hp1;
                u64 k  = fma2(fma2(ym2, NEG1, vp), ym1, fma2(vc, NEG1, F2));
                x[i]   = fma2(k, H6, xa[i]);
                ym2 = ym1; ym1 = vc;
            }
            pb ^= 1;
            sA[pb][t] = x[14]; sB[pb][t] = x[15]; sC[pb][t] = x[0];
            __syncthreads();
        }
    }

    // ---- fused head: logits + log_softmax ----
    float lx[10], ly[10];
#pragma unroll
    for (int o = 0; o < 10; o++) {
        const float4* w4 = (const float4*)(W2 + (size_t)o * 1024 + t * 16);
        u64 a = 0ull;
#pragma unroll
        for (int j = 0; j < 4; j++) {
            float4 w = w4[j];
            a = fma2(x[4 * j + 0], pack2(w.x, w.x), a);
            a = fma2(x[4 * j + 1], pack2(w.y, w.y), a);
            a = fma2(x[4 * j + 2], pack2(w.z, w.z), a);
            a = fma2(x[4 * j + 3], pack2(w.w, w.w), a);
        }
        float2 v = unpack2(a);
#pragma unroll
        for (int off = 16; off > 0; off >>= 1) {
            v.x += __shfl_xor_sync(0xFFFFFFFFu, v.x, off);
            v.y += __shfl_xor_sync(0xFFFFFFFFu, v.y, off);
        }
        lx[o] = v.x; ly[o] = v.y;
    }
    if ((t & 31) == 0) {
#pragma unroll
        for (int o = 0; o < 10; o++) red[warp][o] = make_float2(lx[o], ly[o]);
    }
    __syncthreads();
    if (t < 10) {
        float gx = red[0][t].x + red[1][t].x + b2[t];
        float gy = red[0][t].y + red[1][t].y + b2[t];
        lg[t] = make_float2(gx, gy);
    }
    __syncthreads();
    if (t < 2) {
        float m = -1e30f;
#pragma unroll
        for (int o = 0; o < 10; o++) {
            float v = (t == 0) ? lg[o].x : lg[o].y;
            m = fmaxf(m, v);
        }
        float sum = 0.0f;
#pragma unroll
        for (int o = 0; o < 10; o++) {
            float v = (t == 0) ? lg[o].x : lg[o].y;
            sum += expf(v - m);
        }
        lse2[t] = logf(sum) + m;
    }
    __syncthreads();
    if (t < 10) {
        out[(size_t)(2 * blockIdx.x) * 10 + t]     = lg[t].x - lse2[0];
        out[(size_t)(2 * blockIdx.x + 1) * 10 + t] = lg[t].y - lse2[1];
    }
}

// ---------------------------------------------------------------------------
extern "C" void kernel_launch(void* const* d_in, const int* in_sizes, int n_in,
                              void* d_out, int out_size)
{
    const float* x  = (const float*)d_in[0];  // [8192, 784]
    const float* W1 = (const float*)d_in[1];  // [1024, 784]
    const float* b1 = (const float*)d_in[2];  // [1024]
    const float* W2 = (const float*)d_in[3];  // [10, 1024]
    const float* b2 = (const float*)d_in[4];  // [10]
    float* out = (float*)d_out;               // [8192, 10]

    cudaFuncSetAttribute(gemm1_mma, cudaFuncAttributeMaxDynamicSharedMemorySize, GEMM_SMEM);

    dim3 g1(1024 / 128, 8192 / 128);          // (8, 64)
    gemm1_mma<<<g1, 128, GEMM_SMEM>>>(x, W1, b1);
    rk4_head_kernel<<<8192 / 2, 64>>>(W2, b2, out);
}